// round 1
// baseline (speedup 1.0000x reference)
#include <cuda_runtime.h>

#define DIN  64
#define DOUT 64
#define HH   32
#define HP   16          // h-pairs
#define BB   2048

// ---- device scratch (no allocations allowed) ----
// w1p: [o][i][hp][16 floats] = {w_f0(h0),w_f0(h1), ..., w_f6(h0),w_f6(h1), pad, pad}
__device__ __align__(16) unsigned long long g_w1p[DOUT * DIN * HP * 8];   // 4 MB
// bw:  [o][i][hp][4 floats]  = {B1(h0),B1(h1), W2(h0),W2(h1)}
__device__ __align__(16) unsigned long long g_bw[DOUT * DIN * HP * 2];    // 1 MB
__device__ float g_xT[DIN * BB];
__device__ float g_sumB2[DOUT];

// ---- f32x2 helpers (packed fp32: 2x FMA throughput, PTX-only) ----
__device__ __forceinline__ unsigned long long pack2(float a, float b) {
    unsigned long long v;
    asm("mov.b64 %0, {%1, %2};" : "=l"(v) : "f"(a), "f"(b));
    return v;
}
__device__ __forceinline__ void unpack2(unsigned long long v, float& a, float& b) {
    asm("mov.b64 {%0, %1}, %2;" : "=f"(a), "=f"(b) : "l"(v));
}
__device__ __forceinline__ unsigned long long fma2(unsigned long long a,
                                                   unsigned long long b,
                                                   unsigned long long c) {
    unsigned long long d;
    asm("fma.rn.f32x2 %0, %1, %2, %3;" : "=l"(d) : "l"(a), "l"(b), "l"(c));
    return d;
}
__device__ __forceinline__ unsigned long long mul2(unsigned long long a,
                                                   unsigned long long b) {
    unsigned long long d;
    asm("mul.rn.f32x2 %0, %1, %2;" : "=l"(d) : "l"(a), "l"(b));
    return d;
}
__device__ __forceinline__ float tanh_fast(float x) {
    float y;
    asm("tanh.approx.f32 %0, %1;" : "=f"(y) : "f"(x));
    return y;
}

// feats order must match reference concat: [x, sin(1x), sin(2x), sin(4x), cos(1x), cos(2x), cos(4x)]
__device__ __forceinline__ void make_feats(float x, unsigned long long* fp) {
    float s1 = __sinf(x),  c1 = __cosf(x);
    float x2 = x + x;
    float s2 = __sinf(x2), c2 = __cosf(x2);
    float x4 = x2 + x2;
    float s4 = __sinf(x4), c4 = __cosf(x4);
    fp[0] = pack2(x,  x);
    fp[1] = pack2(s1, s1);
    fp[2] = pack2(s2, s2);
    fp[3] = pack2(s4, s4);
    fp[4] = pack2(c1, c1);
    fp[5] = pack2(c2, c2);
    fp[6] = pack2(c4, c4);
}

// ---- prologue kernels ----
__global__ void prep_x(const float* __restrict__ x) {
    int t = blockIdx.x * blockDim.x + threadIdx.x;
    if (t >= DIN * BB) return;
    int b = t & (BB - 1);
    int i = t >> 11;
    g_xT[t] = x[b * DIN + i];   // coalesced write, strided read (one-time, tiny)
}

__global__ void prep_b2(const float* __restrict__ B2) {
    int o = threadIdx.x;
    if (o >= DOUT) return;
    float s = 0.f;
    for (int i = 0; i < DIN; i++) s += B2[i * DOUT + o];
    g_sumB2[o] = s;
}

__global__ void repack(const float* __restrict__ W1, const float* __restrict__ W2,
                       const float* __restrict__ B1) {
    int t = blockIdx.x * blockDim.x + threadIdx.x;  // t = o*1024 + i*16 + hp
    if (t >= DOUT * DIN * HP) return;
    int hp = t & 15;
    int i  = (t >> 4) & 63;
    int o  = t >> 10;
    int h0 = hp * 2, h1 = h0 + 1;

    const float* w1b = W1 + (((size_t)i * DOUT + o) * HH) * 7;  // W1[i][o][h][f]
    float* dst = ((float*)g_w1p) + (size_t)t * 16;
#pragma unroll
    for (int f = 0; f < 7; f++) {
        dst[2 * f]     = w1b[h0 * 7 + f];
        dst[2 * f + 1] = w1b[h1 * 7 + f];
    }
    dst[14] = 0.f; dst[15] = 0.f;

    const float* b1b = B1 + ((size_t)i * DOUT + o) * HH;
    const float* w2b = W2 + ((size_t)i * DOUT + o) * HH;  // W2[i][o][0][h]
    float* d2 = ((float*)g_bw) + (size_t)t * 4;
    d2[0] = b1b[h0]; d2[1] = b1b[h1];
    d2[2] = w2b[h0]; d2[3] = w2b[h1];
}

// ---- main fused kernel ----
// 1 warp = (64 b's, 1 o). lane owns b = base+lane and base+32+lane.
// f32x2 packing is across the h-pair: acc(h0,h1) += wpair * (f,f).
__global__ void __launch_bounds__(128) kan_main(float* __restrict__ out) {
    int lane = threadIdx.x & 31;
    int W    = blockIdx.x * 4 + (threadIdx.x >> 5);   // 2048 warp-tasks
    int o    = W & 63;
    int bblk = W >> 6;                                 // 0..31
    int bA   = bblk * 64 + lane;
    int bB   = bA + 32;

    const ulonglong2* wbase  = ((const ulonglong2*)g_w1p) + (size_t)o * (DIN * HP * 4);
    const ulonglong2* bwbase = ((const ulonglong2*)g_bw)  + (size_t)o * (DIN * HP);

    const unsigned long long HALF2 = pack2(0.5f, 0.5f);
    unsigned long long outA = 0ull, outB = 0ull;   // pack(0,0)
    unsigned long long fpA[7], fpB[7];

    for (int i = 0; i < DIN; i++) {
        float xa = g_xT[i * BB + bA];
        float xb = g_xT[i * BB + bB];
        make_feats(xa, fpA);
        make_feats(xb, fpB);

        const ulonglong2* wr = wbase  + i * (HP * 4);
        const ulonglong2* br = bwbase + i * HP;

#pragma unroll 2
        for (int hp = 0; hp < HP; hp++) {
            ulonglong2 q0 = wr[hp * 4 + 0];
            ulonglong2 q1 = wr[hp * 4 + 1];
            ulonglong2 q2 = wr[hp * 4 + 2];
            ulonglong2 q3 = wr[hp * 4 + 3];
            ulonglong2 bv = br[hp];          // .x = B1 pair, .y = W2 pair

            // ---- b = bA ----
            unsigned long long a = fma2(q0.x, fpA[0], bv.x);
            a = fma2(q0.y, fpA[1], a);
            a = fma2(q1.x, fpA[2], a);
            a = fma2(q1.y, fpA[3], a);
            a = fma2(q2.x, fpA[4], a);
            a = fma2(q2.y, fpA[5], a);
            a = fma2(q3.x, fpA[6], a);
            unsigned long long ha = mul2(a, HALF2);
            float h0, h1;
            unpack2(ha, h0, h1);
            unsigned long long tp = pack2(tanh_fast(h0), tanh_fast(h1));
            unsigned long long sa = fma2(ha, tp, ha);   // silu = x/2 + (x/2)tanh(x/2)
            outA = fma2(sa, bv.y, outA);

            // ---- b = bB ----
            unsigned long long c = fma2(q0.x, fpB[0], bv.x);
            c = fma2(q0.y, fpB[1], c);
            c = fma2(q1.x, fpB[2], c);
            c = fma2(q1.y, fpB[3], c);
            c = fma2(q2.x, fpB[4], c);
            c = fma2(q2.y, fpB[5], c);
            c = fma2(q3.x, fpB[6], c);
            unsigned long long hb = mul2(c, HALF2);
            float g0, g1;
            unpack2(hb, g0, g1);
            unsigned long long tq = pack2(tanh_fast(g0), tanh_fast(g1));
            unsigned long long sb = fma2(hb, tq, hb);
            outB = fma2(sb, bv.y, outB);
        }
    }

    float a0, a1, b0, b1;
    unpack2(outA, a0, a1);
    unpack2(outB, b0, b1);
    float sb2 = g_sumB2[o];
    out[bA * DOUT + o] = a0 + a1 + sb2;
    out[bB * DOUT + o] = b0 + b1 + sb2;
}

extern "C" void kernel_launch(void* const* d_in, const int* in_sizes, int n_in,
                              void* d_out, int out_size) {
    const float* x  = (const float*)d_in[0];
    const float* W1 = (const float*)d_in[1];
    const float* W2 = (const float*)d_in[2];
    const float* B1 = (const float*)d_in[3];
    const float* B2 = (const float*)d_in[4];
    (void)in_sizes; (void)n_in; (void)out_size;

    prep_x<<<(DIN * BB + 255) / 256, 256>>>(x);
    repack<<<(DOUT * DIN * HP + 255) / 256, 256>>>(W1, W2, B1);
    prep_b2<<<1, 64>>>(B2);
    kan_main<<<512, 128>>>((float*)d_out);
}

// round 2
// speedup vs baseline: 1.6742x; 1.6742x over previous
#include <cuda_runtime.h>

#define DIN  64
#define DOUT 64
#define HH   32
#define HP   16          // h-pairs
#define BB   2048
#define IQ   4           // Din split factor (4 partial kernels' worth of occupancy)
#define IPQ  (DIN / IQ)  // 16 i's per CTA

// ---- device scratch (no allocations allowed) ----
// w1p: [o][i][hp][16 floats] = {w_f0(h0),w_f0(h1), ..., w_f6(h0),w_f6(h1), pad, pad}
__device__ __align__(16) unsigned long long g_w1p[DOUT * DIN * HP * 8];   // 4 MB
// bw:  [o][i][hp][4 floats]  = {B1(h0),B1(h1), W2(h0),W2(h1)}
__device__ __align__(16) unsigned long long g_bw[DOUT * DIN * HP * 2];    // 1 MB
__device__ float g_xT[DIN * BB];
__device__ float g_sumB2[DOUT];
__device__ float g_part[IQ * BB * DOUT];                                   // 2 MB partials

// ---- f32x2 helpers (packed fp32: 2x FMA throughput, PTX-only) ----
__device__ __forceinline__ unsigned long long pack2(float a, float b) {
    unsigned long long v;
    asm("mov.b64 %0, {%1, %2};" : "=l"(v) : "f"(a), "f"(b));
    return v;
}
__device__ __forceinline__ void unpack2(unsigned long long v, float& a, float& b) {
    asm("mov.b64 {%0, %1}, %2;" : "=f"(a), "=f"(b) : "l"(v));
}
__device__ __forceinline__ unsigned long long fma2(unsigned long long a,
                                                   unsigned long long b,
                                                   unsigned long long c) {
    unsigned long long d;
    asm("fma.rn.f32x2 %0, %1, %2, %3;" : "=l"(d) : "l"(a), "l"(b), "l"(c));
    return d;
}
__device__ __forceinline__ unsigned long long mul2(unsigned long long a,
                                                   unsigned long long b) {
    unsigned long long d;
    asm("mul.rn.f32x2 %0, %1, %2;" : "=l"(d) : "l"(a), "l"(b));
    return d;
}
__device__ __forceinline__ unsigned long long add2(unsigned long long a,
                                                   unsigned long long b) {
    unsigned long long d;
    asm("add.rn.f32x2 %0, %1, %2;" : "=l"(d) : "l"(a), "l"(b));
    return d;
}
__device__ __forceinline__ float tanh_fast(float x) {
    float y;
    asm("tanh.approx.f32 %0, %1;" : "=f"(y) : "f"(x));
    return y;
}

// feats order matches reference concat: [x, sin(1x), sin(2x), sin(4x), cos(1x), cos(2x), cos(4x)]
__device__ __forceinline__ void make_feats(float x, unsigned long long* fp) {
    float s1 = __sinf(x),  c1 = __cosf(x);
    float x2 = x + x;
    float s2 = __sinf(x2), c2 = __cosf(x2);
    float x4 = x2 + x2;
    float s4 = __sinf(x4), c4 = __cosf(x4);
    fp[0] = pack2(x,  x);
    fp[1] = pack2(s1, s1);
    fp[2] = pack2(s2, s2);
    fp[3] = pack2(s4, s4);
    fp[4] = pack2(c1, c1);
    fp[5] = pack2(c2, c2);
    fp[6] = pack2(c4, c4);
}

// ---- prologue kernels ----
__global__ void prep_x(const float* __restrict__ x) {
    int t = blockIdx.x * blockDim.x + threadIdx.x;
    if (t >= DIN * BB) return;
    int b = t & (BB - 1);
    int i = t >> 11;
    g_xT[t] = x[b * DIN + i];
}

__global__ void prep_b2(const float* __restrict__ B2) {
    int o = threadIdx.x;
    if (o >= DOUT) return;
    float s = 0.f;
    for (int i = 0; i < DIN; i++) s += B2[i * DOUT + o];
    g_sumB2[o] = s;
}

__global__ void repack(const float* __restrict__ W1, const float* __restrict__ W2,
                       const float* __restrict__ B1) {
    int t = blockIdx.x * blockDim.x + threadIdx.x;  // t = o*1024 + i*16 + hp
    if (t >= DOUT * DIN * HP) return;
    int hp = t & 15;
    int i  = (t >> 4) & 63;
    int o  = t >> 10;
    int h0 = hp * 2, h1 = h0 + 1;

    const float* w1b = W1 + (((size_t)i * DOUT + o) * HH) * 7;  // W1[i][o][h][f]
    float* dst = ((float*)g_w1p) + (size_t)t * 16;
#pragma unroll
    for (int f = 0; f < 7; f++) {
        dst[2 * f]     = w1b[h0 * 7 + f];
        dst[2 * f + 1] = w1b[h1 * 7 + f];
    }
    dst[14] = 0.f; dst[15] = 0.f;

    const float* b1b = B1 + ((size_t)i * DOUT + o) * HH;
    const float* w2b = W2 + ((size_t)i * DOUT + o) * HH;  // W2[i][o][0][h]
    float* d2 = ((float*)g_bw) + (size_t)t * 4;
    d2[0] = b1b[h0]; d2[1] = b1b[h1];
    d2[2] = w2b[h0]; d2[3] = w2b[h1];
}

// ---- main fused kernel ----
// CTA = 8 warps, ONE o, one quarter of Din (16 i's), 512 b's (64 per warp, 2/lane).
// grid = 64 o * 4 bgroup * 4 iq = 1024 CTAs -> 8192 warps.
// All warps in a CTA stream the same 20KB weight slice -> L1 broadcast hits.
__global__ void __launch_bounds__(256) kan_main() {
    int lane = threadIdx.x & 31;
    int w    = threadIdx.x >> 5;
    int o    = blockIdx.x & 63;
    int bg   = (blockIdx.x >> 6) & 3;
    int iq   = blockIdx.x >> 8;
    int bA   = bg * 512 + w * 64 + lane;
    int bB   = bA + 32;
    int i0   = iq * IPQ;

    const ulonglong2* wbase  = ((const ulonglong2*)g_w1p) + ((size_t)o * DIN + i0) * (HP * 4);
    const ulonglong2* bwbase = ((const ulonglong2*)g_bw)  + ((size_t)o * DIN + i0) * HP;

    const unsigned long long HALF2 = pack2(0.5f, 0.5f);
    unsigned long long outA = 0ull, outB = 0ull;
    unsigned long long fpA[7], fpB[7];

    for (int ii = 0; ii < IPQ; ii++) {
        float xa = g_xT[(i0 + ii) * BB + bA];
        float xb = g_xT[(i0 + ii) * BB + bB];
        make_feats(xa, fpA);
        make_feats(xb, fpB);

        const ulonglong2* wr = wbase  + ii * (HP * 4);
        const ulonglong2* br = bwbase + ii * HP;

#pragma unroll 4
        for (int hp = 0; hp < HP; hp++) {
            ulonglong2 q0 = wr[hp * 4 + 0];
            ulonglong2 q1 = wr[hp * 4 + 1];
            ulonglong2 q2 = wr[hp * 4 + 2];
            ulonglong2 q3 = wr[hp * 4 + 3];
            ulonglong2 bv = br[hp];          // .x = B1 pair, .y = W2 pair

            // ---- b = bA : two-accumulator tree (depth ~5 instead of 9) ----
            unsigned long long u = fma2(q0.x, fpA[0], bv.x);
            unsigned long long v = mul2(q0.y, fpA[1]);
            u = fma2(q1.x, fpA[2], u);
            v = fma2(q1.y, fpA[3], v);
            u = fma2(q2.x, fpA[4], u);
            v = fma2(q2.y, fpA[5], v);
            u = fma2(q3.x, fpA[6], u);
            unsigned long long a = add2(u, v);
            unsigned long long ha = mul2(a, HALF2);
            float h0, h1;
            unpack2(ha, h0, h1);
            unsigned long long tp = pack2(tanh_fast(h0), tanh_fast(h1));
            unsigned long long sa = fma2(ha, tp, ha);   // silu = x/2 + (x/2)tanh(x/2)
            outA = fma2(sa, bv.y, outA);

            // ---- b = bB ----
            unsigned long long p = fma2(q0.x, fpB[0], bv.x);
            unsigned long long r = mul2(q0.y, fpB[1]);
            p = fma2(q1.x, fpB[2], p);
            r = fma2(q1.y, fpB[3], r);
            p = fma2(q2.x, fpB[4], p);
            r = fma2(q2.y, fpB[5], r);
            p = fma2(q3.x, fpB[6], p);
            unsigned long long c = add2(p, r);
            unsigned long long hb = mul2(c, HALF2);
            float g0, g1;
            unpack2(hb, g0, g1);
            unsigned long long tq = pack2(tanh_fast(g0), tanh_fast(g1));
            unsigned long long sb = fma2(hb, tq, hb);
            outB = fma2(sb, bv.y, outB);
        }
    }

    float a0, a1, b0, b1;
    unpack2(outA, a0, a1);
    unpack2(outB, b0, b1);
    g_part[((size_t)iq * BB + bA) * DOUT + o] = a0 + a1;
    g_part[((size_t)iq * BB + bB) * DOUT + o] = b0 + b1;
}

// ---- epilogue: sum 4 partials + bias ----
__global__ void epilogue(float* __restrict__ out) {
    int t = blockIdx.x * 256 + threadIdx.x;
    if (t >= BB * DOUT) return;
    int o = t & 63;
    float s = g_sumB2[o];
    s += g_part[t];
    s += g_part[BB * DOUT + t];
    s += g_part[2 * BB * DOUT + t];
    s += g_part[3 * BB * DOUT + t];
    out[t] = s;
}

extern "C" void kernel_launch(void* const* d_in, const int* in_sizes, int n_in,
                              void* d_out, int out_size) {
    const float* x  = (const float*)d_in[0];
    const float* W1 = (const float*)d_in[1];
    const float* W2 = (const float*)d_in[2];
    const float* B1 = (const float*)d_in[3];
    const float* B2 = (const float*)d_in[4];
    (void)in_sizes; (void)n_in; (void)out_size;

    prep_x<<<(DIN * BB + 255) / 256, 256>>>(x);
    repack<<<(DOUT * DIN * HP + 255) / 256, 256>>>(W1, W2, B1);
    prep_b2<<<1, 64>>>(B2);
    kan_main<<<DOUT * 4 * IQ, 256>>>();
    epilogue<<<(BB * DOUT + 255) / 256, 256>>>((float*)d_out);
}

// round 3
// speedup vs baseline: 2.1266x; 1.2702x over previous
#include <cuda_runtime.h>

#define DIN  64
#define DOUT 64
#define HH   32
#define HP   16          // h-pairs
#define BB   2048
#define IQ   4           // Din split factor
#define IPQ  (DIN / IQ)  // 16 i's per warp-task

// ---- device scratch ----
// w1p record per (o,i,hp): 64B = {0.5*w_f(h0),0.5*w_f(h1) for f=0..6, 0.5*B1(h0),0.5*B1(h1)}
__device__ __align__(16) unsigned long long g_w1p[DOUT * DIN * HP * 8];   // 4 MB
// w2: per (o,i): 16 hp-pairs of W2 = 128B
__device__ __align__(16) unsigned long long g_w2[DOUT * DIN * HP];        // 1 MB
__device__ float g_xT[DIN * BB];
__device__ float g_sumB2[DOUT];
__device__ float g_part[IQ * BB * DOUT];                                   // 2 MB

// ---- f32x2 helpers ----
__device__ __forceinline__ unsigned long long pack2(float a, float b) {
    unsigned long long v;
    asm("mov.b64 %0, {%1, %2};" : "=l"(v) : "f"(a), "f"(b));
    return v;
}
__device__ __forceinline__ void unpack2(unsigned long long v, float& a, float& b) {
    asm("mov.b64 {%0, %1}, %2;" : "=f"(a), "=f"(b) : "l"(v));
}
__device__ __forceinline__ unsigned long long fma2(unsigned long long a,
                                                   unsigned long long b,
                                                   unsigned long long c) {
    unsigned long long d;
    asm("fma.rn.f32x2 %0, %1, %2, %3;" : "=l"(d) : "l"(a), "l"(b), "l"(c));
    return d;
}
__device__ __forceinline__ unsigned long long mul2(unsigned long long a,
                                                   unsigned long long b) {
    unsigned long long d;
    asm("mul.rn.f32x2 %0, %1, %2;" : "=l"(d) : "l"(a), "l"(b));
    return d;
}
__device__ __forceinline__ unsigned long long add2(unsigned long long a,
                                                   unsigned long long b) {
    unsigned long long d;
    asm("add.rn.f32x2 %0, %1, %2;" : "=l"(d) : "l"(a), "l"(b));
    return d;
}
__device__ __forceinline__ float tanh_fast(float x) {
    float y;
    asm("tanh.approx.f32 %0, %1;" : "=f"(y) : "f"(x));
    return y;
}

// feats order matches reference: [x, sin(1x), sin(2x), sin(4x), cos(1x), cos(2x), cos(4x)]
__device__ __forceinline__ void make_feats(float x, unsigned long long* fp) {
    float s1 = __sinf(x),  c1 = __cosf(x);
    float x2 = x + x;
    float s2 = __sinf(x2), c2 = __cosf(x2);
    float x4 = x2 + x2;
    float s4 = __sinf(x4), c4 = __cosf(x4);
    fp[0] = pack2(x,  x);
    fp[1] = pack2(s1, s1);
    fp[2] = pack2(s2, s2);
    fp[3] = pack2(s4, s4);
    fp[4] = pack2(c1, c1);
    fp[5] = pack2(c2, c2);
    fp[6] = pack2(c4, c4);
}

// one edge-MLP evaluation for one b (h-pair packed), weights pre-scaled by 0.5
__device__ __forceinline__ void edge_eval(ulonglong2 q0, ulonglong2 q1,
                                          ulonglong2 q2, ulonglong2 q3,
                                          unsigned long long w2p,
                                          const unsigned long long* f,
                                          unsigned long long& acc) {
    unsigned long long u = fma2(q0.x, f[0], q3.y);  // q3.y = 0.5*B1 pair
    unsigned long long v = mul2(q0.y, f[1]);
    u = fma2(q1.x, f[2], u);
    v = fma2(q1.y, f[3], v);
    u = fma2(q2.x, f[4], u);
    v = fma2(q2.y, f[5], v);
    u = fma2(q3.x, f[6], u);
    unsigned long long a = add2(u, v);              // a = h/2
    float a0, a1;
    unpack2(a, a0, a1);
    unsigned long long tp = pack2(tanh_fast(a0), tanh_fast(a1));
    unsigned long long s = fma2(a, tp, a);          // silu(h) = (h/2)(1+tanh(h/2))
    acc = fma2(s, w2p, acc);
}

// ---- prologue kernels ----
__global__ void prep_x(const float* __restrict__ x) {
    int t = blockIdx.x * blockDim.x + threadIdx.x;
    if (t >= DIN * BB) return;
    int b = t & (BB - 1);
    int i = t >> 11;
    g_xT[t] = x[b * DIN + i];
}

__global__ void prep_b2(const float* __restrict__ B2) {
    int o = threadIdx.x;
    if (o >= DOUT) return;
    float s = 0.f;
    for (int i = 0; i < DIN; i++) s += B2[i * DOUT + o];
    g_sumB2[o] = s;
}

__global__ void repack(const float* __restrict__ W1, const float* __restrict__ W2,
                       const float* __restrict__ B1) {
    int t = blockIdx.x * blockDim.x + threadIdx.x;  // t = o*1024 + i*16 + hp
    if (t >= DOUT * DIN * HP) return;
    int hp = t & 15;
    int i  = (t >> 4) & 63;
    int o  = t >> 10;
    int h0 = hp * 2, h1 = h0 + 1;

    const float* w1b = W1 + (((size_t)i * DOUT + o) * HH) * 7;  // W1[i][o][h][f]
    float* dst = ((float*)g_w1p) + (size_t)t * 16;
#pragma unroll
    for (int f = 0; f < 7; f++) {
        dst[2 * f]     = 0.5f * w1b[h0 * 7 + f];
        dst[2 * f + 1] = 0.5f * w1b[h1 * 7 + f];
    }
    const float* b1b = B1 + ((size_t)i * DOUT + o) * HH;
    dst[14] = 0.5f * b1b[h0];
    dst[15] = 0.5f * b1b[h1];

    const float* w2b = W2 + ((size_t)i * DOUT + o) * HH;  // W2[i][o][0][h]
    float* d2 = ((float*)g_w2) + (((size_t)o * DIN + i) * HP + hp) * 2;
    d2[0] = w2b[h0];
    d2[1] = w2b[h1];
}

// ---- main fused kernel ----
// warp = (128 b's, 1 o, 16 i's). lane owns 4 b's. CTA = 8 warps, same (o,iq),
// consecutive b-blocks -> all 8 warps stream the same 18KB weight slice (L1 hits).
// grid = 64 o * 4 iq * 2 = 512 CTAs, 4096 warps.
__global__ void __launch_bounds__(256, 2) kan_main() {
    int lane = threadIdx.x & 31;
    int w    = threadIdx.x >> 5;
    int o    = blockIdx.x & 63;
    int iq   = (blockIdx.x >> 6) & 3;
    int half = blockIdx.x >> 8;
    int bblk = half * 8 + w;                 // 0..15
    int b0   = bblk * 128 + lane;
    int i0   = iq * IPQ;

    const ulonglong2* wbase  = ((const ulonglong2*)g_w1p) + ((size_t)o * DIN + i0) * (HP * 4);
    const ulonglong2* w2base = ((const ulonglong2*)g_w2)  + ((size_t)o * DIN + i0) * (HP / 2);

    unsigned long long accA = 0ull, accB = 0ull, accC = 0ull, accD = 0ull;
    unsigned long long fA[7], fB[7], fC[7], fD[7];

    for (int ii = 0; ii < IPQ; ii++) {
        const float* xr = g_xT + (i0 + ii) * BB + b0;
        make_feats(xr[0],  fA);
        make_feats(xr[32], fB);
        make_feats(xr[64], fC);
        make_feats(xr[96], fD);

        const ulonglong2* wr  = wbase  + ii * (HP * 4);
        const ulonglong2* w2r = w2base + ii * (HP / 2);

#pragma unroll 2
        for (int hpp = 0; hpp < HP / 2; hpp++) {
            ulonglong2 w2q = w2r[hpp];      // W2 pairs for hp=2hpp (.x) and 2hpp+1 (.y)
#pragma unroll
            for (int k = 0; k < 2; k++) {
                int hp = 2 * hpp + k;
                ulonglong2 q0 = wr[hp * 4 + 0];
                ulonglong2 q1 = wr[hp * 4 + 1];
                ulonglong2 q2 = wr[hp * 4 + 2];
                ulonglong2 q3 = wr[hp * 4 + 3];
                unsigned long long w2p = k ? w2q.y : w2q.x;
                edge_eval(q0, q1, q2, q3, w2p, fA, accA);
                edge_eval(q0, q1, q2, q3, w2p, fB, accB);
                edge_eval(q0, q1, q2, q3, w2p, fC, accC);
                edge_eval(q0, q1, q2, q3, w2p, fD, accD);
            }
        }
    }

    float r0, r1;
    float* pp = g_part + (size_t)iq * BB * DOUT;
    unpack2(accA, r0, r1); pp[(b0      ) * DOUT + o] = r0 + r1;
    unpack2(accB, r0, r1); pp[(b0 + 32 ) * DOUT + o] = r0 + r1;
    unpack2(accC, r0, r1); pp[(b0 + 64 ) * DOUT + o] = r0 + r1;
    unpack2(accD, r0, r1); pp[(b0 + 96 ) * DOUT + o] = r0 + r1;
}

// ---- epilogue: sum 4 partials + bias ----
__global__ void epilogue(float* __restrict__ out) {
    int t = blockIdx.x * 256 + threadIdx.x;
    if (t >= BB * DOUT) return;
    int o = t & 63;
    float s = g_sumB2[o];
    s += g_part[t];
    s += g_part[BB * DOUT + t];
    s += g_part[2 * BB * DOUT + t];
    s += g_part[3 * BB * DOUT + t];
    out[t] = s;
}

extern "C" void kernel_launch(void* const* d_in, const int* in_sizes, int n_in,
                              void* d_out, int out_size) {
    const float* x  = (const float*)d_in[0];
    const float* W1 = (const float*)d_in[1];
    const float* W2 = (const float*)d_in[2];
    const float* B1 = (const float*)d_in[3];
    const float* B2 = (const float*)d_in[4];
    (void)in_sizes; (void)n_in; (void)out_size;

    prep_x<<<(DIN * BB + 255) / 256, 256>>>(x);
    repack<<<(DOUT * DIN * HP + 255) / 256, 256>>>(W1, W2, B1);
    prep_b2<<<1, 64>>>(B2);
    kan_main<<<512, 256>>>();
    epilogue<<<(BB * DOUT + 255) / 256, 256>>>((float*)d_out);
}

// round 4
// speedup vs baseline: 2.8047x; 1.3189x over previous
#include <cuda_runtime.h>

#define DIN  64
#define DOUT 64
#define HH   32
#define HP   16          // h-pairs
#define BB   2048
#define IQ   4           // Din split factor
#define IPQ  (DIN / IQ)  // 16 i's per CTA

// ---- device scratch ----
// w1p record per (o,i,hp): 64B = {0.5*w_f(h0),0.5*w_f(h1) f=0..6, 0.5*B1(h0),0.5*B1(h1)}
__device__ __align__(16) unsigned long long g_w1p[DOUT * DIN * HP * 8];   // 4 MB
// w2: per (o,i): 16 hp-pairs of W2 = 128B
__device__ __align__(16) unsigned long long g_w2[DOUT * DIN * HP];        // 1 MB
__device__ float g_xT[DIN * BB];
__device__ float g_sumB2[DOUT];
__device__ float g_part[IQ * BB * DOUT];                                   // 2 MB

// ---- f32x2 helpers ----
__device__ __forceinline__ unsigned long long pack2(float a, float b) {
    unsigned long long v;
    asm("mov.b64 %0, {%1, %2};" : "=l"(v) : "f"(a), "f"(b));
    return v;
}
__device__ __forceinline__ void unpack2(unsigned long long v, float& a, float& b) {
    asm("mov.b64 {%0, %1}, %2;" : "=f"(a), "=f"(b) : "l"(v));
}
__device__ __forceinline__ unsigned long long fma2(unsigned long long a,
                                                   unsigned long long b,
                                                   unsigned long long c) {
    unsigned long long d;
    asm("fma.rn.f32x2 %0, %1, %2, %3;" : "=l"(d) : "l"(a), "l"(b), "l"(c));
    return d;
}
__device__ __forceinline__ unsigned long long mul2(unsigned long long a,
                                                   unsigned long long b) {
    unsigned long long d;
    asm("mul.rn.f32x2 %0, %1, %2;" : "=l"(d) : "l"(a), "l"(b));
    return d;
}
__device__ __forceinline__ unsigned long long add2(unsigned long long a,
                                                   unsigned long long b) {
    unsigned long long d;
    asm("add.rn.f32x2 %0, %1, %2;" : "=l"(d) : "l"(a), "l"(b));
    return d;
}
__device__ __forceinline__ float tanh_fast(float x) {
    float y;
    asm("tanh.approx.f32 %0, %1;" : "=f"(y) : "f"(x));
    return y;
}

// feats order matches reference: [x, sin(1x), sin(2x), sin(4x), cos(1x), cos(2x), cos(4x)]
__device__ __forceinline__ void make_feats(float x, unsigned long long* fp) {
    float s1 = __sinf(x),  c1 = __cosf(x);
    float x2 = x + x;
    float s2 = __sinf(x2), c2 = __cosf(x2);
    float x4 = x2 + x2;
    float s4 = __sinf(x4), c4 = __cosf(x4);
    fp[0] = pack2(x,  x);
    fp[1] = pack2(s1, s1);
    fp[2] = pack2(s2, s2);
    fp[3] = pack2(s4, s4);
    fp[4] = pack2(c1, c1);
    fp[5] = pack2(c2, c2);
    fp[6] = pack2(c4, c4);
}

// one edge-MLP evaluation for one b (h-pair packed), weights pre-scaled by 0.5
__device__ __forceinline__ void edge_eval(ulonglong2 q0, ulonglong2 q1,
                                          ulonglong2 q2, ulonglong2 q3,
                                          unsigned long long w2p,
                                          const unsigned long long* f,
                                          unsigned long long& acc) {
    unsigned long long u = fma2(q0.x, f[0], q3.y);  // q3.y = 0.5*B1 pair
    unsigned long long v = mul2(q0.y, f[1]);
    u = fma2(q1.x, f[2], u);
    v = fma2(q1.y, f[3], v);
    u = fma2(q2.x, f[4], u);
    v = fma2(q2.y, f[5], v);
    u = fma2(q3.x, f[6], u);
    unsigned long long a = add2(u, v);              // a = h/2
    float a0, a1;
    unpack2(a, a0, a1);
    unsigned long long tp = pack2(tanh_fast(a0), tanh_fast(a1));
    unsigned long long s = fma2(a, tp, a);          // silu(h) = (h/2)(1+tanh(h/2))
    acc = fma2(s, w2p, acc);
}

// ---- prologue kernels ----
__global__ void prep_x(const float* __restrict__ x) {
    int t = blockIdx.x * blockDim.x + threadIdx.x;
    if (t >= DIN * BB) return;
    int b = t & (BB - 1);
    int i = t >> 11;
    g_xT[t] = x[b * DIN + i];
}

__global__ void prep_b2(const float* __restrict__ B2) {
    int o = threadIdx.x;
    if (o >= DOUT) return;
    float s = 0.f;
    for (int i = 0; i < DIN; i++) s += B2[i * DOUT + o];
    g_sumB2[o] = s;
}

__global__ void repack(const float* __restrict__ W1, const float* __restrict__ W2,
                       const float* __restrict__ B1) {
    int t = blockIdx.x * blockDim.x + threadIdx.x;  // t = o*1024 + i*16 + hp
    if (t >= DOUT * DIN * HP) return;
    int hp = t & 15;
    int i  = (t >> 4) & 63;
    int o  = t >> 10;
    int h0 = hp * 2, h1 = h0 + 1;

    const float* w1b = W1 + (((size_t)i * DOUT + o) * HH) * 7;  // W1[i][o][h][f]
    float* dst = ((float*)g_w1p) + (size_t)t * 16;
#pragma unroll
    for (int f = 0; f < 7; f++) {
        dst[2 * f]     = 0.5f * w1b[h0 * 7 + f];
        dst[2 * f + 1] = 0.5f * w1b[h1 * 7 + f];
    }
    const float* b1b = B1 + ((size_t)i * DOUT + o) * HH;
    dst[14] = 0.5f * b1b[h0];
    dst[15] = 0.5f * b1b[h1];

    const float* w2b = W2 + ((size_t)i * DOUT + o) * HH;  // W2[i][o][0][h]
    float* d2 = ((float*)g_w2) + (((size_t)o * DIN + i) * HP + hp) * 2;
    d2[0] = w2b[h0];
    d2[1] = w2b[h1];
}

// ---- main fused kernel ----
// CTA = 8 warps, one (o, iq, b-quarter). Weights for the 16-i slice live in smem
// (18KB), broadcast-LDS in the hot loop. Lane owns 2 b's. 3 CTAs/SM.
// grid = 64 o * 4 iq * 4 bq = 1024 CTAs, 8192 warps.
__global__ void __launch_bounds__(256, 3) kan_main() {
    __shared__ __align__(16) ulonglong2 s_w1[IPQ * HP * 4];   // 16 KB
    __shared__ __align__(16) ulonglong2 s_w2[IPQ * HP / 2];   // 2 KB

    int lane = threadIdx.x & 31;
    int w    = threadIdx.x >> 5;
    int o    = blockIdx.x & 63;
    int iq   = (blockIdx.x >> 6) & 3;
    int bq   = blockIdx.x >> 8;             // 0..3
    int b0   = bq * 512 + w * 64 + lane;
    int i0   = iq * IPQ;

    // cooperative weight-slice load (contiguous, coalesced LDG.128)
    {
        const ulonglong2* gw1 = ((const ulonglong2*)g_w1p) + ((size_t)o * DIN + i0) * (HP * 4);
        const ulonglong2* gw2 = ((const ulonglong2*)g_w2)  + ((size_t)o * DIN + i0) * (HP / 2);
#pragma unroll
        for (int t = threadIdx.x; t < IPQ * HP * 4; t += 256) s_w1[t] = gw1[t];
        if (threadIdx.x < IPQ * HP / 2) s_w2[threadIdx.x] = gw2[threadIdx.x];
    }
    __syncthreads();

    unsigned long long accA = 0ull, accB = 0ull;
    unsigned long long fA[7], fB[7];

    for (int ii = 0; ii < IPQ; ii++) {
        const float* xr = g_xT + (i0 + ii) * BB + b0;
        make_feats(xr[0],  fA);
        make_feats(xr[32], fB);

        const ulonglong2* wr  = s_w1 + ii * (HP * 4);
        const ulonglong2* w2r = s_w2 + ii * (HP / 2);

#pragma unroll 2
        for (int hpp = 0; hpp < HP / 2; hpp++) {
            ulonglong2 w2q = w2r[hpp];      // W2 pairs for hp=2hpp (.x), 2hpp+1 (.y)
#pragma unroll
            for (int k = 0; k < 2; k++) {
                int hp = 2 * hpp + k;
                ulonglong2 q0 = wr[hp * 4 + 0];
                ulonglong2 q1 = wr[hp * 4 + 1];
                ulonglong2 q2 = wr[hp * 4 + 2];
                ulonglong2 q3 = wr[hp * 4 + 3];
                unsigned long long w2p = k ? w2q.y : w2q.x;
                edge_eval(q0, q1, q2, q3, w2p, fA, accA);
                edge_eval(q0, q1, q2, q3, w2p, fB, accB);
            }
        }
    }

    float r0, r1;
    float* pp = g_part + (size_t)iq * BB * DOUT;
    unpack2(accA, r0, r1); pp[(b0     ) * DOUT + o] = r0 + r1;
    unpack2(accB, r0, r1); pp[(b0 + 32) * DOUT + o] = r0 + r1;
}

// ---- epilogue: sum 4 partials + bias ----
__global__ void epilogue(float* __restrict__ out) {
    int t = blockIdx.x * 256 + threadIdx.x;
    if (t >= BB * DOUT) return;
    int o = t & 63;
    float s = g_sumB2[o];
    s += g_part[t];
    s += g_part[BB * DOUT + t];
    s += g_part[2 * BB * DOUT + t];
    s += g_part[3 * BB * DOUT + t];
    out[t] = s;
}

extern "C" void kernel_launch(void* const* d_in, const int* in_sizes, int n_in,
                              void* d_out, int out_size) {
    const float* x  = (const float*)d_in[0];
    const float* W1 = (const float*)d_in[1];
    const float* W2 = (const float*)d_in[2];
    const float* B1 = (const float*)d_in[3];
    const float* B2 = (const float*)d_in[4];
    (void)in_sizes; (void)n_in; (void)out_size;

    prep_x<<<(DIN * BB + 255) / 256, 256>>>(x);
    repack<<<(DOUT * DIN * HP + 255) / 256, 256>>>(W1, W2, B1);
    prep_b2<<<1, 64>>>(B2);
    kan_main<<<1024, 256>>>();
    epilogue<<<(BB * DOUT + 255) / 256, 256>>>((float*)d_out);
}